// round 5
// baseline (speedup 1.0000x reference)
#include <cuda_runtime.h>
#include <cuda_fp16.h>

#define BATCH   256
#define IN_DIM  65536
#define OUT_DIM 65536

// tiles
#define NT_T  1024   // transpose tiles per half: 512 i-tiles x 2 b-tiles
#define NT_C  256    // coef tiles
#define NT_I  512    // idx tiles
#define NT_M  2048   // main tiles per half (32 neurons each)
#define NP1   (NT_T + NT_C + NT_I)   // 1792
#define NP2   (NT_T + NT_M)          // 3072

// ---------------- device scratch ----------------------------------------
__device__ float4 g_coef[OUT_DIM];                             // 1 MB
__device__ __align__(16) __half g_xth[(size_t)IN_DIM * BATCH]; // 32 MB
__device__ int    g_idx[2 * OUT_DIM];                          // 512 KB
__device__ unsigned g_count = 0;
__device__ volatile unsigned g_sense = 0;

// ---- sense-reversing global barrier (grid fully resident; 2 uses/launch
//      -> g_sense returns to 0 so graph replays are safe) ----------------
__device__ __forceinline__ void global_bar(unsigned& sense) {
    __threadfence();                 // publish this block's prior stores
    __syncthreads();
    if (threadIdx.x == 0) {
        sense ^= 1u;
        unsigned pos = atomicAdd(&g_count, 1u);
        if (pos == gridDim.x - 1) {
            g_count = 0;
            __threadfence();
            g_sense = sense;
        } else {
            while (g_sense != sense) __nanosleep(64);
        }
    }
    __syncthreads();
}

// ---------------- tile bodies -------------------------------------------
__device__ __forceinline__ void do_transpose(float* t /*[4][64][33]*/,
                                             const float* __restrict__ x,
                                             int id, int half, int tid) {
    int i0 = (id >> 1) * 128;
    int b0 = half * 128 + (id & 1) * 64;
    int tx = tid & 7, ty = tid >> 3;

    const float4* r0 = (const float4*)(x + (size_t)(b0 + ty)      * IN_DIM + i0);
    const float4* r1 = (const float4*)(x + (size_t)(b0 + 32 + ty) * IN_DIM + i0);
    float4 v0[4], v1[4];
    #pragma unroll
    for (int h = 0; h < 4; h++) {
        v0[h] = __ldcs(r0 + tx + 8 * h);
        v1[h] = __ldcs(r1 + tx + 8 * h);
    }
    #pragma unroll
    for (int h = 0; h < 4; h++) {
        float* th = t + h * (64 * 33);
        th[(ty     ) * 33 + tx*4+0] = v0[h].x; th[(ty     ) * 33 + tx*4+1] = v0[h].y;
        th[(ty     ) * 33 + tx*4+2] = v0[h].z; th[(ty     ) * 33 + tx*4+3] = v0[h].w;
        th[(ty + 32) * 33 + tx*4+0] = v1[h].x; th[(ty + 32) * 33 + tx*4+1] = v1[h].y;
        th[(ty + 32) * 33 + tx*4+2] = v1[h].z; th[(ty + 32) * 33 + tx*4+3] = v1[h].w;
    }
    __syncthreads();
    #pragma unroll
    for (int h = 0; h < 4; h++) {
        const float* th = t + h * (64 * 33);
        union { uint4 u; __half2 hh[4]; } pk;
        #pragma unroll
        for (int k = 0; k < 4; k++)
            pk.hh[k] = __floats2half2_rn(th[(8*tx + 2*k) * 33 + ty],
                                         th[(8*tx + 2*k + 1) * 33 + ty]);
        *(uint4*)(g_xth + (size_t)(i0 + 32*h + ty) * BATCH + b0 + 8*tx) = pk.u;
    }
    __syncthreads();
}

__device__ __forceinline__ void do_coef(const float* __restrict__ wts, int o) {
    float p[16];
    const float4* w4 = (const float4*)(wts + (size_t)o * 16);
    float4 q0 = w4[0], q1 = w4[1], q2 = w4[2], q3 = w4[3];
    p[0]=q0.x; p[1]=q0.y; p[2]=q0.z; p[3]=q0.w;
    p[4]=q1.x; p[5]=q1.y; p[6]=q1.z; p[7]=q1.w;
    p[8]=q2.x; p[9]=q2.y; p[10]=q2.z; p[11]=q2.w;
    p[12]=q3.x; p[13]=q3.y; p[14]=q3.z; p[15]=q3.w;
    float m = p[0];
    #pragma unroll
    for (int i = 1; i < 16; i++) m = fmaxf(m, p[i]);
    float s = 0.f;
    #pragma unroll
    for (int i = 0; i < 16; i++) { p[i] = __expf(p[i] - m); s += p[i]; }
    float inv = 1.0f / s;
    #pragma unroll
    for (int i = 0; i < 16; i++) p[i] *= inv;
    float4 c;
    c.x = p[8]+p[9]+p[10]+p[11]+p[12]+p[13]+p[14]+p[15];
    c.y = p[2]+p[3]+p[6]+p[7]-p[8]-p[9]-p[12]-p[13];
    c.z = p[4]+p[5]+p[6]+p[7]-p[8]-p[9]-p[10]-p[11];
    c.w = p[1]-p[2]-p[4]-2.f*p[6]-p[7]+p[8]+2.f*p[9]+p[11]+p[13]-p[14];
    g_coef[o] = c;
}

// main tile: 32 neurons x 128 batches (one half). 8 warps x 4 neurons.
__device__ __forceinline__ void do_mtile(float* s /*[128*32]*/,
                                         float* __restrict__ out,
                                         int id, int half, int tid) {
    int ob = id * 32;
    int w = tid >> 5, l = tid & 31;
    int n0 = w * 4;

    int ia[4], ib[4];
    #pragma unroll
    for (int c = 0; c < 4; c++) {
        ia[c] = g_idx[ob + n0 + c];
        ib[c] = g_idx[OUT_DIM + ob + n0 + c];
    }
    uint2 va[4], vb[4];
    #pragma unroll
    for (int c = 0; c < 4; c++) {
        va[c] = ((const uint2*)(g_xth + (size_t)ia[c] * BATCH + half * 128))[l];
        vb[c] = ((const uint2*)(g_xth + (size_t)ib[c] * BATCH + half * 128))[l];
    }

    #pragma unroll
    for (int c = 0; c < 4; c++) {
        float4 cf = g_coef[ob + n0 + c];
        union { uint2 u; __half2 h[2]; } A, Bv;
        A.u = va[c]; Bv.u = vb[c];
        int n = n0 + c;
        int col = (n + l) & 31;                 // bb>>2 == l for bb=4l+k
        #pragma unroll
        for (int k2 = 0; k2 < 2; k2++) {
            float2 a = __half22float2(A.h[k2]);
            float2 b = __half22float2(Bv.h[k2]);
            float v0 = fmaf(fmaf(cf.w, b.x, cf.y), a.x, fmaf(cf.z, b.x, cf.x));
            float v1 = fmaf(fmaf(cf.w, b.y, cf.y), a.y, fmaf(cf.z, b.y, cf.x));
            int bb = 4 * l + 2 * k2;
            s[bb * 32 + col]       = v0;        // bank = (n+l)&31: conflict-free
            s[(bb + 1) * 32 + col] = v1;
        }
    }
    __syncthreads();

    #pragma unroll
    for (int j = 0; j < 16; j++) {
        int bb = w * 16 + j;
        int col = (l + (bb >> 2)) & 31;         // bank = l+const: conflict-free
        __stcs(out + (size_t)(half * 128 + bb) * OUT_DIM + ob + l,
               s[bb * 32 + col]);
    }
    __syncthreads();
}

// ---------------- fused persistent kernel -------------------------------
__global__ __launch_bounds__(256) void fused_kernel(const float* __restrict__ x,
                                                    const float* __restrict__ wts,
                                                    const void*  __restrict__ idxraw,
                                                    float* __restrict__ out) {
    __shared__ __align__(16) float smem[4 * 64 * 33];   // 33792 B (>= 128*32 main)
    unsigned sense = 0;
    int tid = threadIdx.x;

    // index dtype detection (once, cached reads)
    int is64 = 1;
    {
        const long long* p = (const long long*)idxraw;
        #pragma unroll 1
        for (int j = 0; j < 64; j++) {
            long long v = __ldg(p + j);
            if (v < 0 || v >= IN_DIM) { is64 = 0; break; }
        }
    }

    // phase 1: transpose half 0, coef, idx
    for (int t = blockIdx.x; t < NP1; t += gridDim.x) {
        if (t < NT_T) do_transpose(smem, x, t, 0, tid);
        else if (t < NT_T + NT_C) do_coef(wts, (t - NT_T) * 256 + tid);
        else {
            int i = (t - NT_T - NT_C) * 256 + tid;
            g_idx[i] = is64 ? (int)((const long long*)idxraw)[i]
                            : ((const int*)idxraw)[i];
        }
    }
    global_bar(sense);

    // phase 2: transpose half 1 overlapped with main half 0
    for (int t = blockIdx.x; t < NP2; t += gridDim.x) {
        if (t < NT_T) do_transpose(smem, x, t, 1, tid);
        else          do_mtile(smem, out, t - NT_T, 0, tid);
    }
    global_bar(sense);

    // phase 3: main half 1
    for (int t = blockIdx.x; t < NT_M; t += gridDim.x)
        do_mtile(smem, out, t, 1, tid);
}

// ---------------- launch ------------------------------------------------
extern "C" void kernel_launch(void* const* d_in, const int* in_sizes, int n_in,
                              void* d_out, int out_size) {
    const float* x   = (const float*)d_in[0];
    const float* wts = (const float*)d_in[1];
    const void*  idx = d_in[2];
    float* out = (float*)d_out;

    int dev = 0;
    cudaGetDevice(&dev);
    int sms = 148;
    cudaDeviceGetAttribute(&sms, cudaDevAttrMultiProcessorCount, dev);
    int occ = 0;
    cudaOccupancyMaxActiveBlocksPerMultiprocessor(&occ, fused_kernel, 256, 0);
    if (occ < 1) occ = 1;
    if (occ > 8) occ = 8;
    int grid = sms * occ;   // exactly occ blocks/SM -> all resident, barrier-safe

    fused_kernel<<<grid, 256>>>(x, wts, idx, out);
}

// round 6
// speedup vs baseline: 1.1481x; 1.1481x over previous
#include <cuda_runtime.h>
#include <cuda_fp16.h>

#define BATCH   256
#define IN_DIM  65536
#define OUT_DIM 65536

#define NB_T 2048   // transpose blocks: (IN/128) x (B/64)
#define NB_C 256    // coef blocks
#define NB_I 512    // idx-convert blocks

// ---------------- device scratch (no allocation allowed) ----------------
__device__ float4 g_coef[OUT_DIM];                             // 1 MB
__device__ __align__(16) __half g_xth[(size_t)IN_DIM * BATCH]; // 32 MB: x^T fp16 [IN][B]
__device__ int    g_idx[2 * OUT_DIM];                          // 512 KB

// ---------------- fused prep: transpose + coef + idx convert ------------
__global__ __launch_bounds__(256) void prep_kernel(const float* __restrict__ x,
                                                   const float* __restrict__ wts,
                                                   const void*  __restrict__ idxraw) {
    __shared__ float t[4][64][33];
    int bx  = blockIdx.x;
    int tid = threadIdx.x;

    if (bx < NB_T) {
        // tile: 128 inputs x 64 batches; 8 float4 loads in flight per thread
        int it = bx & 511, bt = bx >> 9;
        int i0 = it * 128, b0 = bt * 64;
        int tx = tid & 7, ty = tid >> 3;

        const float4* r0 = (const float4*)(x + (size_t)(b0 + ty)      * IN_DIM + i0);
        const float4* r1 = (const float4*)(x + (size_t)(b0 + 32 + ty) * IN_DIM + i0);
        float4 v0[4], v1[4];
        #pragma unroll
        for (int h = 0; h < 4; h++) {
            v0[h] = __ldcs(r0 + tx + 8 * h);
            v1[h] = __ldcs(r1 + tx + 8 * h);
        }
        #pragma unroll
        for (int h = 0; h < 4; h++) {
            t[h][ty   ][tx*4+0]=v0[h].x; t[h][ty   ][tx*4+1]=v0[h].y;
            t[h][ty   ][tx*4+2]=v0[h].z; t[h][ty   ][tx*4+3]=v0[h].w;
            t[h][ty+32][tx*4+0]=v1[h].x; t[h][ty+32][tx*4+1]=v1[h].y;
            t[h][ty+32][tx*4+2]=v1[h].z; t[h][ty+32][tx*4+3]=v1[h].w;
        }
        __syncthreads();
        #pragma unroll
        for (int h = 0; h < 4; h++) {
            union { uint4 u; __half2 hh[4]; } pk;
            #pragma unroll
            for (int k = 0; k < 4; k++)
                pk.hh[k] = __floats2half2_rn(t[h][8*tx + 2*k][ty], t[h][8*tx + 2*k + 1][ty]);
            *(uint4*)(g_xth + (size_t)(i0 + 32*h + ty) * BATCH + b0 + 8*tx) = pk.u;
        }
    } else if (bx < NB_T + NB_C) {
        // softmax -> bilinear coefficients
        int o = (bx - NB_T) * 256 + tid;
        float p[16];
        const float4* w4 = (const float4*)(wts + (size_t)o * 16);
        float4 q0 = w4[0], q1 = w4[1], q2 = w4[2], q3 = w4[3];
        p[0]=q0.x; p[1]=q0.y; p[2]=q0.z; p[3]=q0.w;
        p[4]=q1.x; p[5]=q1.y; p[6]=q1.z; p[7]=q1.w;
        p[8]=q2.x; p[9]=q2.y; p[10]=q2.z; p[11]=q2.w;
        p[12]=q3.x; p[13]=q3.y; p[14]=q3.z; p[15]=q3.w;
        float m = p[0];
        #pragma unroll
        for (int i = 1; i < 16; i++) m = fmaxf(m, p[i]);
        float s = 0.f;
        #pragma unroll
        for (int i = 0; i < 16; i++) { p[i] = __expf(p[i] - m); s += p[i]; }
        float inv = 1.0f / s;
        #pragma unroll
        for (int i = 0; i < 16; i++) p[i] *= inv;
        float4 c;
        c.x = p[8]+p[9]+p[10]+p[11]+p[12]+p[13]+p[14]+p[15];
        c.y = p[2]+p[3]+p[6]+p[7]-p[8]-p[9]-p[12]-p[13];
        c.z = p[4]+p[5]+p[6]+p[7]-p[8]-p[9]-p[10]-p[11];
        c.w = p[1]-p[2]-p[4]-2.f*p[6]-p[7]+p[8]+2.f*p[9]+p[11]+p[13]-p[14];
        g_coef[o] = c;
    } else {
        // idx convert with per-block dtype detection
        __shared__ int s64;
        if (tid == 0) {
            const long long* p = (const long long*)idxraw;
            int is64 = 1;
            #pragma unroll 1
            for (int j = 0; j < 64; j++) {
                long long v = p[j];
                if (v < 0 || v >= IN_DIM) { is64 = 0; break; }
            }
            s64 = is64;
        }
        __syncthreads();
        int i = (bx - NB_T - NB_C) * 256 + tid;
        g_idx[i] = s64 ? (int)((const long long*)idxraw)[i]
                       : ((const int*)idxraw)[i];
    }
}

// ---------------- main: 16 warps x 2 neurons per 512-thread block -------
// Block = 32 neurons x 256 batches. Each lane loads one uint4 (8 halves) of
// each of 4 rows (2 neurons x {a,b}); 32-bit byte offsets into the 32MB
// table keep addressing in single registers. Staging smem swizzle:
//   store  s[bb*32 + ((n + l) & 31)]   (banks n+l: lane-bijective)
//   read   s[bb*32 + ((l + (bb>>3)) & 31)] (banks l+const: lane-bijective)
__global__ __launch_bounds__(512, 3) void logic_main_kernel(float* __restrict__ out) {
    __shared__ float s[BATCH * 32];           // 32 KB
    int tid = threadIdx.x;
    int w = tid >> 5;                         // 0..15
    int l = tid & 31;
    int ob = blockIdx.x * 32;
    int n0 = w * 2;

    const char* base = (const char*)g_xth;
    unsigned lane16 = (unsigned)l * 16u;
    unsigned oa0 = (unsigned)__ldg(&g_idx[ob + n0    ]) * 512u + lane16;
    unsigned oa1 = (unsigned)__ldg(&g_idx[ob + n0 + 1]) * 512u + lane16;
    unsigned ob0 = (unsigned)__ldg(&g_idx[OUT_DIM + ob + n0    ]) * 512u + lane16;
    unsigned ob1 = (unsigned)__ldg(&g_idx[OUT_DIM + ob + n0 + 1]) * 512u + lane16;

    union { uint4 u; __half2 h[4]; } A0, B0, A1, B1;
    A0.u = *(const uint4*)(base + oa0);
    B0.u = *(const uint4*)(base + ob0);
    A1.u = *(const uint4*)(base + oa1);
    B1.u = *(const uint4*)(base + ob1);

    float4 c0 = __ldg(&g_coef[ob + n0]);
    float4 c1 = __ldg(&g_coef[ob + n0 + 1]);

    int bbase = 8 * l;
    int col0 = (n0 + l) & 31;                 // bb>>3 == l for all our bb
    int col1 = (n0 + 1 + l) & 31;
    #pragma unroll
    for (int k2 = 0; k2 < 4; k2++) {
        float2 a = __half22float2(A0.h[k2]);
        float2 b = __half22float2(B0.h[k2]);
        int bb = bbase + 2 * k2;
        s[bb * 32 + col0]       = fmaf(fmaf(c0.w, b.x, c0.y), a.x, fmaf(c0.z, b.x, c0.x));
        s[(bb + 1) * 32 + col0] = fmaf(fmaf(c0.w, b.y, c0.y), a.y, fmaf(c0.z, b.y, c0.x));
    }
    #pragma unroll
    for (int k2 = 0; k2 < 4; k2++) {
        float2 a = __half22float2(A1.h[k2]);
        float2 b = __half22float2(B1.h[k2]);
        int bb = bbase + 2 * k2;
        s[bb * 32 + col1]       = fmaf(fmaf(c1.w, b.x, c1.y), a.x, fmaf(c1.z, b.x, c1.x));
        s[(bb + 1) * 32 + col1] = fmaf(fmaf(c1.w, b.y, c1.y), a.y, fmaf(c1.z, b.y, c1.x));
    }
    __syncthreads();

    // warp w writes batch rows 16w..16w+15, 128B-coalesced, streaming
    #pragma unroll
    for (int j = 0; j < 16; j++) {
        int bb = w * 16 + j;
        __stcs(out + (size_t)bb * OUT_DIM + ob + l,
               s[bb * 32 + ((l + (bb >> 3)) & 31)]);
    }
}

// ---------------- launch ------------------------------------------------
extern "C" void kernel_launch(void* const* d_in, const int* in_sizes, int n_in,
                              void* d_out, int out_size) {
    const float* x   = (const float*)d_in[0];
    const float* wts = (const float*)d_in[1];
    const void*  idx = d_in[2];
    float* out = (float*)d_out;

    prep_kernel<<<NB_T + NB_C + NB_I, 256>>>(x, wts, idx);
    logic_main_kernel<<<OUT_DIM / 32, 512>>>(out);
}